// round 17
// baseline (speedup 1.0000x reference)
#include <cuda_runtime.h>
#include <cuda_bf16.h>
#include <cstdint>
#include <math.h>

// Problem dims: B=64, T=512, V=512, E=128, D=256
constexpr int Tn = 512, Bn = 64, Vn = 512, En = 128, Dn = 256;
constexpr int TT = 16;

typedef unsigned long long u64;
typedef __nv_bfloat16 bf16;

// fp32 scratch
__device__ float g_xp [Tn*Bn*Dn];
__device__ float g_H  [Tn*Bn*Dn];
__device__ float g_P  [Tn*Bn*Dn];
__device__ float g_C  [Tn*Bn*Dn];
__device__ float g_Wt [Dn*Dn];

// split-bf16 scratch
__device__ bf16 g_Hb_hi [Tn*Bn*Dn];
__device__ bf16 g_Hb_lo [Tn*Bn*Dn];
__device__ bf16 g_Xb_hi [Tn*Bn*Dn];
__device__ bf16 g_Xb_lo [Tn*Bn*Dn];
__device__ bf16 g_WaT_hi[Dn*Dn];
__device__ bf16 g_WaT_lo[Dn*Dn];
__device__ bf16 g_UaT_hi[Dn*Dn];
__device__ bf16 g_UaT_lo[Dn*Dn];
__device__ bf16 g_fcWT_hi[Vn*2*Dn];
__device__ bf16 g_fcWT_lo[Vn*2*Dn];
__device__ bf16 g_WihT_hi[Dn*En];
__device__ bf16 g_WihT_lo[Dn*En];
__device__ bf16 g_Eb_hi [Vn*En];
__device__ bf16 g_Eb_lo [Vn*En];

// packed f32x2 fma
#define FMA2(acc, a, w) \
    asm("fma.rn.f32x2 %0, %1, %2, %0;" : "+l"(acc) : "l"(a), "l"(w))

__device__ __forceinline__ unsigned smem_u32(const void* p) {
    return (unsigned)__cvta_generic_to_shared(p);
}
__device__ __forceinline__ float hadd2(u64 v) {
    unsigned lo, hi;
    asm("mov.b64 {%0,%1}, %2;" : "=r"(lo), "=r"(hi) : "l"(v));
    return __uint_as_float(lo) + __uint_as_float(hi);
}

// ---------------- mma.sync helpers (baseline PTX, sm_80+) ----------------
#define LDSM_X4(r0_, r1_, r2_, r3_, addr) \
    asm volatile("ldmatrix.sync.aligned.m8n8.x4.shared.b16 {%0,%1,%2,%3}, [%4];" \
        : "=r"(r0_), "=r"(r1_), "=r"(r2_), "=r"(r3_) : "r"(addr))

#define MMA16816(d, a, b) \
    asm volatile("mma.sync.aligned.m16n8k16.row.col.f32.bf16.bf16.f32 " \
        "{%0,%1,%2,%3}, {%4,%5,%6,%7}, {%8,%9}, {%0,%1,%2,%3};" \
        : "+f"((d)[0]), "+f"((d)[1]), "+f"((d)[2]), "+f"((d)[3]) \
        : "r"((a)[0]), "r"((a)[1]), "r"((a)[2]), "r"((a)[3]), \
          "r"((b)[0]), "r"((b)[1]))

// ---------------------------------------------------------------------------
// 0) transpose W_hh
__global__ void k_transpose(const float* __restrict__ W) {
    int k = blockIdx.x, d = threadIdx.x;
    g_Wt[d*Dn + k] = W[k*Dn + d];
}

__device__ __forceinline__ void split_bf16(float x, bf16& h, bf16& l) {
    h = __float2bfloat16(x);
    l = __float2bfloat16(x - __bfloat162float(h));
}

// ---------------------------------------------------------------------------
// 0b) ALL weight conversions in one kernel (region-decoded).
__global__ void __launch_bounds__(256) k_cvt_all(
    const float* __restrict__ Wa, const float* __restrict__ Ua,
    const float* __restrict__ fcW, const float* __restrict__ Wih,
    const float* __restrict__ E)
{
    int idx = blockIdx.x*256 + threadIdx.x;
    bf16 h, l;
    if (idx < 65536) {                       // WaT: N=256, K=256
        int n = idx >> 8, k = idx & 255;
        split_bf16(Wa[k*Dn + n], h, l);
        g_WaT_hi[idx] = h; g_WaT_lo[idx] = l;
    } else if (idx < 131072) {               // UaT
        int lcl = idx - 65536;
        int n = lcl >> 8, k = lcl & 255;
        split_bf16(Ua[k*Dn + n], h, l);
        g_UaT_hi[lcl] = h; g_UaT_lo[lcl] = l;
    } else if (idx < 393216) {               // fcWT: N=512, K=512
        int lcl = idx - 131072;
        int n = lcl >> 9, k = lcl & 511;
        split_bf16(fcW[k*Vn + n], h, l);
        g_fcWT_hi[lcl] = h; g_fcWT_lo[lcl] = l;
    } else if (idx < 425984) {               // WihT: N=256, K=128
        int lcl = idx - 393216;
        int n = lcl >> 7, k = lcl & 127;
        split_bf16(Wih[k*Dn + n], h, l);
        g_WihT_hi[lcl] = h; g_WihT_lo[lcl] = l;
    } else {                                 // embed: straight split
        int lcl = idx - 425984;
        split_bf16(E[lcl], h, l);
        g_Eb_hi[lcl] = h; g_Eb_lo[lcl] = l;
    }
}

// ---------------------------------------------------------------------------
// 2) Recurrence, one CTA of 512 threads per batch row.
//    Thread (d = tid&255, half = tid>>8) holds W[d][half*128 .. +128) entirely
//    in registers (32 ulonglong2 = 64 regs) and computes a 128-elem partial.
//    Partials combined via smem; tid<256 applies xp + tanh and stores h.
__global__ void __launch_bounds__(512, 1) k_rnn() {
    __shared__ float hbuf[2*256];
    __shared__ float part[512];
    int b = blockIdx.x, tid = threadIdx.x;
    int d = tid & 255, half = tid >> 8;

    const float* wtrow = &g_Wt[d*Dn + half*128];
    ulonglong2 wreg[32];                    // 128 floats = 64 regs
#pragma unroll
    for (int i = 0; i < 32; i++) wreg[i] = *(const ulonglong2*)(wtrow + 4*i);
    if (tid < 512) { }                       // (no-op)
    if (tid < 256) { hbuf[tid] = 0.f; hbuf[256 + tid] = 0.f; }
    __syncthreads();

    for (int t = 0; t < Tn; t++) {
        const float* hp = hbuf + (t & 1) * 256 + half * 128;
        u64 c0 = 0, c1 = 0, c2 = 0, c3 = 0;
#pragma unroll
        for (int i = 0; i < 32; i += 2) {
            ulonglong2 h0 = *(const ulonglong2*)&hp[4*i];
            FMA2(c0, h0.x, wreg[i].x);   FMA2(c1, h0.y, wreg[i].y);
            ulonglong2 h1 = *(const ulonglong2*)&hp[4*(i+1)];
            FMA2(c2, h1.x, wreg[i+1].x); FMA2(c3, h1.y, wreg[i+1].y);
        }
        part[tid] = (hadd2(c0) + hadd2(c1)) + (hadd2(c2) + hadd2(c3));
        __syncthreads();
        if (tid < 256) {
            float hv = tanhf(part[tid] + part[tid + 256]
                             + g_xp[(t*Bn + b)*Dn + d]);
            hbuf[((t & 1) ^ 1) * 256 + d] = hv;
            int gi = (t*Bn + b)*Dn + d;
            g_H[gi] = hv;
            bf16 hh, hl; split_bf16(hv, hh, hl);
            g_Hb_hi[gi] = hh; g_Hb_lo[gi] = hl;
        }
        __syncthreads();
    }
}

// ===========================================================================
// mma.sync split-bf16 GEMM: CTA 128(M)x128(N), 8 warps each 64x32.
// Double-buffered 32-k chunks. 3 passes: hi*hi + hi*lo + lo*hi.
// ===========================================================================
constexpr int MMA_PITCH = 80;
constexpr int MMA_BUF   = 128 * MMA_PITCH;   // 10240 B per tile
constexpr int MMA_SMEM  = 8 * MMA_BUF;       // 2 buffers x 4 tiles = 81920 B

struct MMAArgs {
    const bf16 *Ahi0, *Alo0;
    const bf16 *Ahi1, *Alo1;
    int ksplit;
    int Ka;
    const bf16 *Bhi, *Blo;     // [N][K] row-major
    int Kb;
    int Ktot;
};

__device__ __forceinline__ void stage_chunk(
    char* base, const MMAArgs& g, int r0, int n0, int c,
    const int* __restrict__ ridx, int tid)
{
    int kglob = c * 32;
    const bf16* Ah; const bf16* Al; int ka;
    if (kglob < g.ksplit) { Ah = g.Ahi0; Al = g.Alo0; ka = kglob; }
    else                  { Ah = g.Ahi1; Al = g.Alo1; ka = kglob - g.ksplit; }
    const bf16* srcBh = g.Bhi + (long)n0*g.Kb + kglob;
    const bf16* srcBl = g.Blo + (long)n0*g.Kb + kglob;
    char* sAh = base;
    char* sAl = base + MMA_BUF;
    char* sBh = base + 2*MMA_BUF;
    char* sBl = base + 3*MMA_BUF;
#pragma unroll
    for (int s = 0; s < 2; s++) {
        int idx = tid + s*256;
        int row = idx >> 2, c4 = idx & 3;
        long arow = ridx ? (long)ridx[row] : (long)(r0 + row);
        *(uint4*)(sAh + row*MMA_PITCH + c4*16) = *(const uint4*)(Ah + arow*g.Ka + ka + c4*8);
        *(uint4*)(sAl + row*MMA_PITCH + c4*16) = *(const uint4*)(Al + arow*g.Ka + ka + c4*8);
        *(uint4*)(sBh + row*MMA_PITCH + c4*16) = *(const uint4*)(srcBh + row*g.Kb + c4*8);
        *(uint4*)(sBl + row*MMA_PITCH + c4*16) = *(const uint4*)(srcBl + row*g.Kb + c4*8);
    }
}

__device__ __forceinline__ void mma_gemm_body(
    char* smem, const MMAArgs& g, int r0, int n0, float d[4][4][4],
    const int* __restrict__ ridx)
{
    int tid = threadIdx.x;
    int lane = tid & 31;
    int wid = tid >> 5;
    int wm = (wid & 1) * 64;
    int wn = (wid >> 1) * 32;

    int a_row = lane & 15;
    int a_koff = (lane >> 4) * 16;
    int b_nl  = (lane & 7) + ((lane >> 4) << 3);
    int b_koff = ((lane >> 3) & 1) * 16;

    int nchunks = g.Ktot / 32;
    stage_chunk(smem, g, r0, n0, 0, ridx, tid);
    __syncthreads();

    for (int c = 0; c < nchunks; c++) {
        char* cur = smem + (c & 1) * (4*MMA_BUF);
        if (c + 1 < nchunks)
            stage_chunk(smem + ((c+1) & 1) * (4*MMA_BUF), g, r0, n0, c+1, ridx, tid);

        unsigned uAh = smem_u32(cur);
        unsigned uAl = uAh + MMA_BUF;
        unsigned uBh = uAh + 2*MMA_BUF;
        unsigned uBl = uAh + 3*MMA_BUF;

#pragma unroll
        for (int ks = 0; ks < 2; ks++) {
            int kb = ks * 32;
            unsigned Bhf[4][2], Blf[4][2];
#pragma unroll
            for (int p = 0; p < 2; p++) {
                unsigned rb = (unsigned)((wn + p*16 + b_nl)*MMA_PITCH + b_koff + kb);
                LDSM_X4(Bhf[2*p][0], Bhf[2*p][1], Bhf[2*p+1][0], Bhf[2*p+1][1], uBh + rb);
                LDSM_X4(Blf[2*p][0], Blf[2*p][1], Blf[2*p+1][0], Blf[2*p+1][1], uBl + rb);
            }
#pragma unroll
            for (int f = 0; f < 4; f++) {
                unsigned Ahf[4], Alf[4];
                unsigned ra = (unsigned)((wm + f*16 + a_row)*MMA_PITCH + a_koff + kb);
                LDSM_X4(Ahf[0], Ahf[1], Ahf[2], Ahf[3], uAh + ra);
                LDSM_X4(Alf[0], Alf[1], Alf[2], Alf[3], uAl + ra);
#pragma unroll
                for (int nf = 0; nf < 4; nf++) {
                    MMA16816(d[f][nf], Ahf, Bhf[nf]);
                    MMA16816(d[f][nf], Ahf, Blf[nf]);
                    MMA16816(d[f][nf], Alf, Bhf[nf]);
                }
            }
        }
        __syncthreads();
    }
}

#define ZERO_ACC(d) \
    _Pragma("unroll") for (int f_ = 0; f_ < 4; f_++) \
    _Pragma("unroll") for (int n_ = 0; n_ < 4; n_++) \
    _Pragma("unroll") for (int e_ = 0; e_ < 4; e_++) (d)[f_][n_][e_] = 0.f;

// ---------------------------------------------------------------------------
// 1) xp = embed[x] @ W_ih + b_h  — mma.sync with token gather
__global__ void __launch_bounds__(256) k_embed_mma(
    const int* __restrict__ x, const float* __restrict__ bh)
{
    extern __shared__ char smem[];
    __shared__ int toks[128];
    int r0 = blockIdx.x * 128;
    int n0 = blockIdx.y * 128;
    int tid = threadIdx.x;

    if (tid < 128) {
        int r = r0 + tid, t = r >> 6, b = r & 63;
        toks[tid] = x[b*Tn + t];
    }
    __syncthreads();

    MMAArgs g;
    g.Ahi0 = g_Eb_hi; g.Alo0 = g_Eb_lo; g.Ahi1 = g_Eb_hi; g.Alo1 = g_Eb_lo;
    g.ksplit = 1 << 30; g.Ka = En;
    g.Bhi = g_WihT_hi; g.Blo = g_WihT_lo;
    g.Kb = En; g.Ktot = En;

    float d[4][4][4];
    ZERO_ACC(d)
    mma_gemm_body(smem, g, r0, n0, d, toks);

    int lane = tid & 31, wid = tid >> 5;
    int wm = (wid & 1) * 64, wn = (wid >> 1) * 32;
#pragma unroll
    for (int f = 0; f < 4; f++) {
        int row = r0 + wm + f*16 + (lane >> 2);
#pragma unroll
        for (int nf = 0; nf < 4; nf++) {
            int col = n0 + wn + nf*8 + (lane & 3)*2;
            float2 bv = *(const float2*)&bh[col];
            *(float2*)&g_xp[(long)row*Dn + col]     = make_float2(d[f][nf][0]+bv.x, d[f][nf][1]+bv.y);
            *(float2*)&g_xp[(long)(row+8)*Dn + col] = make_float2(d[f][nf][2]+bv.x, d[f][nf][3]+bv.y);
        }
    }
}

// ---------------------------------------------------------------------------
// 3) P = H @ W_attn (z=0), C = H @ U_attn (z=1)  — mma.sync
__global__ void __launch_bounds__(256) k_proj_mma()
{
    extern __shared__ char smem[];
    int r0 = blockIdx.x * 128;
    int n0 = blockIdx.y * 128;

    MMAArgs g;
    g.Ahi0 = g_Hb_hi; g.Alo0 = g_Hb_lo; g.Ahi1 = g_Hb_hi; g.Alo1 = g_Hb_lo;
    g.ksplit = 1 << 30; g.Ka = Dn;
    g.Bhi = blockIdx.z ? g_UaT_hi : g_WaT_hi;
    g.Blo = blockIdx.z ? g_UaT_lo : g_WaT_lo;
    g.Kb = Dn; g.Ktot = Dn;
    float* Out = blockIdx.z ? g_C : g_P;

    float d[4][4][4];
    ZERO_ACC(d)
    mma_gemm_body(smem, g, r0, n0, d, nullptr);

    int tid = threadIdx.x, lane = tid & 31, wid = tid >> 5;
    int wm = (wid & 1) * 64, wn = (wid >> 1) * 32;
#pragma unroll
    for (int f = 0; f < 4; f++) {
        int row = r0 + wm + f*16 + (lane >> 2);
#pragma unroll
        for (int nf = 0; nf < 4; nf++) {
            int col = n0 + wn + nf*8 + (lane & 3)*2;
            *(float2*)&Out[(long)row*Dn + col]     = make_float2(d[f][nf][0], d[f][nf][1]);
            *(float2*)&Out[(long)(row+8)*Dn + col] = make_float2(d[f][nf][2], d[f][nf][3]);
        }
    }
}

// ---------------------------------------------------------------------------
// 5) logits = [H | CTX] @ fc_W + fc_b  — mma.sync
__global__ void __launch_bounds__(256) k_logits_mma(
    const float* __restrict__ fcb, float* __restrict__ out)
{
    extern __shared__ char smem[];
    int r0 = blockIdx.x * 128;
    int n0 = blockIdx.y * 128;

    MMAArgs g;
    g.Ahi0 = g_Hb_hi; g.Alo0 = g_Hb_lo;
    g.Ahi1 = g_Xb_hi; g.Alo1 = g_Xb_lo;
    g.ksplit = Dn; g.Ka = Dn;
    g.Bhi = g_fcWT_hi; g.Blo = g_fcWT_lo;
    g.Kb = 2*Dn; g.Ktot = 2*Dn;

    float d[4][4][4];
    ZERO_ACC(d)
    mma_gemm_body(smem, g, r0, n0, d, nullptr);

    int tid = threadIdx.x, lane = tid & 31, wid = tid >> 5;
    int wm = (wid & 1) * 64, wn = (wid >> 1) * 32;
#pragma unroll
    for (int f = 0; f < 4; f++) {
        int r1 = r0 + wm + f*16 + (lane >> 2);
        int r2 = r1 + 8;
        int t1 = r1 >> 6, b1 = r1 & 63;
        int t2 = r2 >> 6, b2 = r2 & 63;
        float* o1 = &out[((long)b1*Tn + t1)*Vn];
        float* o2 = &out[((long)b2*Tn + t2)*Vn];
#pragma unroll
        for (int nf = 0; nf < 4; nf++) {
            int col = n0 + wn + nf*8 + (lane & 3)*2;
            float2 bv = *(const float2*)&fcb[col];
            *(float2*)&o1[col] = make_float2(d[f][nf][0] + bv.x, d[f][nf][1] + bv.y);
            *(float2*)&o2[col] = make_float2(d[f][nf][2] + bv.x, d[f][nf][3] + bv.y);
        }
    }
}

// ---------------------------------------------------------------------------
// 4) Bahdanau attention (MUFU floor); pass-3 writes split-bf16 ctx directly.
__global__ void __launch_bounds__(256) k_attn(const float* __restrict__ vat) {
    __shared__ float Cs[TT][Dn - 4];
    __shared__ float Cs2[TT][4];
    __shared__ float EsT[Tn][TT];
    int b  = blockIdx.y;
    int t0 = blockIdx.x * TT;
    int tid = threadIdx.x;
    int warp = tid >> 5, lane = tid & 31;

    for (int idx = tid; idx < TT*Dn; idx += 256) {
        int q = idx / Dn, d2 = idx % Dn;
        float v = g_C[((t0+q)*Bn + b)*Dn + d2];
        if (d2 < Dn - 4) Cs[q][d2] = v; else Cs2[q][d2 - (Dn-4)] = v;
    }
    float vreg[8];
#pragma unroll
    for (int j = 0; j < 8; j++) vreg[j] = vat[lane + 32*j];
    __syncthreads();

    int t_hi = t0 + TT;
    for (int tp = warp; tp < t_hi; tp += 8) {
        float p[8];
#pragma unroll
        for (int j = 0; j < 8; j++) p[j] = g_P[(tp*Bn + b)*Dn + lane + 32*j];
#pragma unroll
        for (int q = 0; q < TT; q++) {
            float s = 0.f;
#pragma unroll
            for (int j = 0; j < 8; j++) {
                int d2 = lane + 32*j;
                float cv = (d2 < Dn - 4) ? Cs[q][d2] : Cs2[q][d2 - (Dn-4)];
                float z = p[j] + cv;
                float th; asm("tanh.approx.f32 %0, %1;" : "=f"(th) : "f"(z));
                s = fmaf(vreg[j], th, s);
            }
#pragma unroll
            for (int o = 16; o; o >>= 1) s += __shfl_xor_sync(0xffffffffu, s, o);
            if (lane == 0) EsT[tp][q] = s;
        }
    }
    __syncthreads();

    for (int q = warp; q < TT; q += 8) {
        int tg = t0 + q;
        float mx = -3.4e38f;
        for (int tp = lane; tp < tg; tp += 32) mx = fmaxf(mx, EsT[tp][q]);
#pragma unroll
        for (int o = 16; o; o >>= 1) mx = fmaxf(mx, __shfl_xor_sync(0xffffffffu, mx, o));
        float sum = 0.f;
        for (int tp = lane; tp < tg; tp += 32) {
            float e = __expf(EsT[tp][q] - mx);
            EsT[tp][q] = e; sum += e;
        }
#pragma unroll
        for (int o = 16; o; o >>= 1) sum += __shfl_xor_sync(0xffffffffu, sum, o);
        float inv = tg > 0 ? 1.f / sum : 0.f;
        for (int tp = lane; tp < t_hi; tp += 32) {
            float wv = (tp < tg) ? EsT[tp][q] * inv : 0.f;
            EsT[tp][q] = wv;
        }
    }
    __syncthreads();

    int d = tid;
    float acc[TT];
#pragma unroll
    for (int q = 0; q < TT; q++) acc[q] = 0.f;
    int tmax = t0 + TT - 1;
    for (int tp = 0; tp < tmax; tp++) {
        float hval = g_H[(tp*Bn + b)*Dn + d];
#pragma unroll
        for (int q = 0; q < TT; q += 4) {
            float4 w = *(const float4*)&EsT[tp][q];
            acc[q]   = fmaf(w.x, hval, acc[q]);
            acc[q+1] = fmaf(w.y, hval, acc[q+1]);
            acc[q+2] = fmaf(w.z, hval, acc[q+2]);
            acc[q+3] = fmaf(w.w, hval, acc[q+3]);
        }
    }
#pragma unroll
    for (int q = 0; q < TT; q++) {
        int tg = t0 + q;
        float c = acc[q];
        if (tg == 0) c = g_H[b*Dn + d];
        int gi = (tg*Bn + b)*Dn + d;
        bf16 hh, hl; split_bf16(c, hh, hl);
        g_Xb_hi[gi] = hh; g_Xb_lo[gi] = hl;
    }
}

// ---------------------------------------------------------------------------
extern "C" void kernel_launch(void* const* d_in, const int* in_sizes, int n_in,
                              void* d_out, int out_size)
{
    const int*   x     = (const int*)  d_in[0];
    const float* embed = (const float*)d_in[1];
    const float* Wih   = (const float*)d_in[2];
    const float* Whh   = (const float*)d_in[3];
    const float* bh    = (const float*)d_in[4];
    const float* Wat   = (const float*)d_in[5];
    const float* Uat   = (const float*)d_in[6];
    const float* vat   = (const float*)d_in[7];
    const float* fcW   = (const float*)d_in[8];
    const float* fcb   = (const float*)d_in[9];
    float* out = (float*)d_out;

    cudaFuncSetAttribute(k_embed_mma,  cudaFuncAttributeMaxDynamicSharedMemorySize, MMA_SMEM);
    cudaFuncSetAttribute(k_proj_mma,   cudaFuncAttributeMaxDynamicSharedMemorySize, MMA_SMEM);
    cudaFuncSetAttribute(k_logits_mma, cudaFuncAttributeMaxDynamicSharedMemorySize, MMA_SMEM);

    k_transpose<<<Dn, Dn>>>(Whh);
    k_cvt_all<<<491520/256, 256>>>(Wat, Uat, fcW, Wih, embed);
    k_embed_mma<<<dim3((Tn*Bn)/128, Dn/128), 256, MMA_SMEM>>>(x, bh);
    k_rnn<<<Bn, 512>>>();
    k_proj_mma<<<dim3((Tn*Bn)/128, Dn/128, 2), 256, MMA_SMEM>>>();
    k_attn<<<dim3(Tn/TT, Bn), 256>>>(vat);
    k_logits_mma<<<dim3((Tn*Bn)/128, Vn/128), 256, MMA_SMEM>>>(fcb, out);
}